// round 4
// baseline (speedup 1.0000x reference)
#include <cuda_runtime.h>
#include <cuda_bf16.h>

#define SIDE 9
#define STATE 81
#define NA 5
#define H 32
#define WARPS 8
#define ROWS 256           // rows per block == threads per block
#define ACPAD 416          // padded action_count row length in smem

// ---------------------------------------------------------------------------
// Packed f32x2 helpers (sm_103a FFMA2)
// ---------------------------------------------------------------------------
__device__ __forceinline__ unsigned long long pack2(float x) {
    unsigned long long r;
    asm("mov.b64 %0, {%1, %1};" : "=l"(r) : "f"(x));
    return r;
}
__device__ __forceinline__ void ffma2(unsigned long long& d,
                                      unsigned long long a,
                                      unsigned long long b) {
    asm("fma.rn.f32x2 %0, %1, %2, %0;" : "+l"(d) : "l"(a), "l"(b));
}
__device__ __forceinline__ void unpack2(unsigned long long p, float& lo, float& hi) {
    asm("mov.b64 {%0, %1}, %2;" : "=f"(lo), "=f"(hi) : "l"(p));
}

// ---------------------------------------------------------------------------
// Fused kernel.
// Phase A (warp-per-row x32): coalesced action_count stage -> scatter-gather
//   nsc -> smem + gmem, reward reduce -> smem + gmem.
// Phase B (thread-per-row): 81->32->32->1 ReLU MLP with FFMA2, reading the
//   warp-private smem nsc rows (only __syncwarp needed between phases).
// ---------------------------------------------------------------------------
__global__ __launch_bounds__(ROWS) void vpn_fused(
    const float* __restrict__ obs,          // (B, 3*STATE)
    const float* __restrict__ acr_g,        // (B, STATE*NA)
    const float* __restrict__ W1,           // (STATE, 32)
    const float* __restrict__ W2,           // (32, 32)
    const float* __restrict__ W3,           // (32, 1)
    const float* __restrict__ b3,           // (1,)
    float* __restrict__ out,                // [sym(B), imm(B), ret(B), nsc(B*81)]
    int B)
{
    extern __shared__ float smem[];
    float* s_nsc = smem;                       // ROWS * STATE
    float* s_ac  = s_nsc + ROWS * STATE;       // WARPS * ACPAD
    float* s_imm = s_ac + WARPS * ACPAD;       // ROWS
    float* sW1   = s_imm + ROWS;               // STATE * H
    float* sW2   = sW1 + STATE * H;            // H * H
    float* sW3   = sW2 + H * H;                // H
    float* sb3   = sW3 + H;                    // 1

    // Stage weights once per block.
    for (int i = threadIdx.x; i < STATE * H; i += blockDim.x) sW1[i] = W1[i];
    for (int i = threadIdx.x; i < H * H; i += blockDim.x)     sW2[i] = W2[i];
    if (threadIdx.x < H)  sW3[threadIdx.x] = W3[threadIdx.x];
    if (threadIdx.x == 0) sb3[0] = b3[0];
    __syncthreads();   // weights visible to every warp's phase B

    const int wid  = threadIdx.x >> 5;
    const int lane = threadIdx.x & 31;
    const long long blockRow0 = (long long)blockIdx.x * ROWS;

    float* __restrict__ sa = s_ac + wid * ACPAD;

    // ---------------- Phase A ----------------
    for (int r = 0; r < 32; r++) {
        const long long row = blockRow0 + wid * 32 + r;
        if (row >= B) break;

        const float* __restrict__ acr = acr_g + row * (STATE * NA);
        #pragma unroll
        for (int k = 0; k < 13; k++) {
            const int i = lane + 32 * k;
            if (i < STATE * NA) sa[i] = __ldg(&acr[i]);
        }
        __syncwarp();

        const float* __restrict__ dem = obs + row * (3 * STATE) + 2 * STATE;
        float* __restrict__ nout = out + 3LL * B + row * STATE;
        float* __restrict__ nrow = s_nsc + (wid * 32 + r) * STATE;

        float imm = 0.0f;
        #pragma unroll
        for (int k = 0; k < 3; k++) {
            const int c = lane + 32 * k;
            if (c < STATE) {
                const int rr  = c / SIDE;
                const int col = c - rr * SIDE;
                float v = sa[c * NA + 0];
                if (rr == 0)        v += sa[c * NA + 1];
                if (rr < SIDE - 1)  v += sa[(c + SIDE) * NA + 1];
                if (rr == SIDE - 1) v += sa[c * NA + 2];
                if (rr > 0)         v += sa[(c - SIDE) * NA + 2];
                if (col == 0)       v += sa[c * NA + 3];
                if (col < SIDE - 1) v += sa[(c + 1) * NA + 3];
                if (col == SIDE-1)  v += sa[c * NA + 4];
                if (col > 0)        v += sa[(c - 1) * NA + 4];

                nrow[c] = v;                      // smem, conflict-free
                nout[c] = v;                      // gmem, coalesced
                imm += fminf(v, __ldg(&dem[c]));  // gmem, coalesced
            }
        }

        #pragma unroll
        for (int o = 16; o; o >>= 1) imm += __shfl_xor_sync(0xffffffffu, imm, o);
        if (lane == 0) {
            out[(long long)B + row] = imm;
            s_imm[wid * 32 + r] = imm;
        }
        __syncwarp();   // sa reads done before restage; nrow/s_imm visible
    }

    // ---------------- Phase B ----------------
    const long long b = blockRow0 + threadIdx.x;
    if (b >= B) return;

    const float* __restrict__ myn = s_nsc + threadIdx.x * STATE;

    unsigned long long h1p[H / 2];
    #pragma unroll
    for (int j = 0; j < H / 2; j++) h1p[j] = 0ULL;

    #pragma unroll 3
    for (int d = 0; d < STATE; d++) {
        const unsigned long long vd = pack2(myn[d]);
        const ulonglong2* __restrict__ w1p =
            reinterpret_cast<const ulonglong2*>(&sW1[d * H]);
        #pragma unroll
        for (int q = 0; q < H / 4; q++) {
            ulonglong2 w = w1p[q];
            ffma2(h1p[q * 2 + 0], vd, w.x);
            ffma2(h1p[q * 2 + 1], vd, w.y);
        }
    }

    float h1[H];
    #pragma unroll
    for (int j = 0; j < H / 2; j++) {
        float lo, hi;
        unpack2(h1p[j], lo, hi);
        h1[2 * j + 0] = fmaxf(lo, 0.0f);
        h1[2 * j + 1] = fmaxf(hi, 0.0f);
    }

    unsigned long long h2p[H / 2];
    #pragma unroll
    for (int j = 0; j < H / 2; j++) h2p[j] = 0ULL;
    #pragma unroll
    for (int i = 0; i < H; i++) {
        const unsigned long long vi = pack2(h1[i]);
        const ulonglong2* __restrict__ w2p =
            reinterpret_cast<const ulonglong2*>(&sW2[i * H]);
        #pragma unroll
        for (int q = 0; q < H / 4; q++) {
            ulonglong2 w = w2p[q];
            ffma2(h2p[q * 2 + 0], vi, w.x);
            ffma2(h2p[q * 2 + 1], vi, w.y);
        }
    }

    float ret = sb3[0];
    #pragma unroll
    for (int j = 0; j < H / 2; j++) {
        float lo, hi;
        unpack2(h2p[j], lo, hi);
        ret = fmaf(fmaxf(lo, 0.0f), sW3[2 * j + 0], ret);
        ret = fmaf(fmaxf(hi, 0.0f), sW3[2 * j + 1], ret);
    }

    const float imm = s_imm[threadIdx.x];
    out[b]                      = imm + ret;  // symbolic_val
    out[2LL * (long long)B + b] = ret;        // next_return
}

static const int FUSED_SMEM_BYTES =
    (ROWS * STATE + WARPS * ACPAD + ROWS + STATE * H + H * H + H + 1) *
    (int)sizeof(float);

extern "C" void kernel_launch(void* const* d_in, const int* in_sizes, int n_in,
                              void* d_out, int out_size) {
    const float* obs = (const float*)d_in[0];
    const float* action_count = (const float*)d_in[1];
    const float* W1 = (const float*)d_in[2];
    const float* W2 = (const float*)d_in[3];
    const float* W3 = (const float*)d_in[4];
    const float* b3 = (const float*)d_in[5];
    float* out = (float*)d_out;

    const int B = in_sizes[0] / (3 * STATE);

    cudaFuncSetAttribute(vpn_fused, cudaFuncAttributeMaxDynamicSharedMemorySize,
                         FUSED_SMEM_BYTES);

    const int blocks = (B + ROWS - 1) / ROWS;
    vpn_fused<<<blocks, ROWS, FUSED_SMEM_BYTES>>>(obs, action_count,
                                                  W1, W2, W3, b3, out, B);
}

// round 5
// speedup vs baseline: 1.9217x; 1.9217x over previous
#include <cuda_runtime.h>
#include <cuda_bf16.h>

#define SIDE 9
#define STATE 81
#define NA 5
#define H 32
#define WARPS_K1 8

#define K2_THREADS 128
#define K2_ROWS    256   // rows per block = 2 per thread

// ---------------------------------------------------------------------------
// K1: warp-per-row scatter + reward (unchanged from round 2/3; ~DRAM bound).
// ---------------------------------------------------------------------------
__global__ __launch_bounds__(32 * WARPS_K1) void k1_nsc_reward(
    const float* __restrict__ obs,          // (B, 3*STATE)
    const float* __restrict__ acr_g,        // (B, STATE*NA)
    float* __restrict__ out,                // [sym(B), imm(B), ret(B), nsc(B*81)]
    int B)
{
    __shared__ float s[WARPS_K1][416];

    const int wid  = threadIdx.x >> 5;
    const int lane = threadIdx.x & 31;
    const long long row = (long long)blockIdx.x * WARPS_K1 + wid;
    if (row >= B) return;

    const float* __restrict__ acr = acr_g + row * (STATE * NA);
    float* __restrict__ sp = s[wid];
    #pragma unroll
    for (int k = 0; k < 13; k++) {
        const int i = lane + 32 * k;
        if (i < STATE * NA) sp[i] = __ldg(&acr[i]);
    }
    __syncwarp();

    const float* __restrict__ dem = obs + row * (3 * STATE) + 2 * STATE;
    float* __restrict__ nout = out + 3LL * B + row * STATE;

    float imm = 0.0f;
    #pragma unroll
    for (int k = 0; k < 3; k++) {
        const int c = lane + 32 * k;
        if (c < STATE) {
            const int r   = c / SIDE;
            const int col = c - r * SIDE;
            float v = sp[c * NA + 0];
            if (r == 0)        v += sp[c * NA + 1];
            if (r < SIDE - 1)  v += sp[(c + SIDE) * NA + 1];
            if (r == SIDE - 1) v += sp[c * NA + 2];
            if (r > 0)         v += sp[(c - SIDE) * NA + 2];
            if (col == 0)      v += sp[c * NA + 3];
            if (col < SIDE - 1)v += sp[(c + 1) * NA + 3];
            if (col == SIDE-1) v += sp[c * NA + 4];
            if (col > 0)       v += sp[(c - 1) * NA + 4];

            nout[c] = v;
            imm += fminf(v, __ldg(&dem[c]));
        }
    }

    #pragma unroll
    for (int o = 16; o; o >>= 1) imm += __shfl_xor_sync(0xffffffffu, imm, o);
    if (lane == 0) out[(long long)B + row] = imm;
}

// ---------------------------------------------------------------------------
// Packed f32x2 helpers (sm_103a FFMA2)
// ---------------------------------------------------------------------------
__device__ __forceinline__ unsigned long long pack2(float x) {
    unsigned long long r;
    asm("mov.b64 %0, {%1, %1};" : "=l"(r) : "f"(x));
    return r;
}
__device__ __forceinline__ void ffma2(unsigned long long& d,
                                      unsigned long long a,
                                      unsigned long long b) {
    asm("fma.rn.f32x2 %0, %1, %2, %0;" : "+l"(d) : "l"(a), "l"(b));
}
__device__ __forceinline__ void unpack2(unsigned long long p, float& lo, float& hi) {
    asm("mov.b64 {%0, %1}, %2;" : "=f"(lo), "=f"(hi) : "l"(p));
}

// ---------------------------------------------------------------------------
// K2: 2 rows per thread. Each weight LDS.128 feeds 4 FFMA2 (2 rows x 2 cols),
// 32 independent accumulator chains per thread. nsc staged block-wide via
// float4 (contiguous, 16B aligned). Rows t and t+128: identical bank
// permutation (17*128 % 32 == 0) -> all LDS conflict-free.
// ---------------------------------------------------------------------------
__global__ __launch_bounds__(K2_THREADS) void k2_mlp(
    const float* __restrict__ W1,
    const float* __restrict__ W2,
    const float* __restrict__ W3,
    const float* __restrict__ b3,
    float* __restrict__ out,
    int B)
{
    extern __shared__ float smem[];
    float* s_nsc = smem;                          // K2_ROWS * STATE
    float* sW1   = s_nsc + K2_ROWS * STATE;       // STATE * H
    float* sW2   = sW1 + STATE * H;               // H * H
    float* sW3   = sW2 + H * H;                   // H
    float* sb3   = sW3 + H;                       // 1

    for (int i = threadIdx.x; i < STATE * H; i += K2_THREADS) sW1[i] = W1[i];
    for (int i = threadIdx.x; i < H * H; i += K2_THREADS)     sW2[i] = W2[i];
    if (threadIdx.x < H)  sW3[threadIdx.x] = W3[threadIdx.x];
    if (threadIdx.x == 0) sb3[0] = b3[0];

    const long long blockRow0 = (long long)blockIdx.x * K2_ROWS;
    const float* __restrict__ nsc_g = out + 3LL * B;

    // Block-wide coalesced float4 stage of 256 contiguous nsc rows.
    if (blockRow0 + K2_ROWS <= B) {
        const float4* __restrict__ src =
            reinterpret_cast<const float4*>(nsc_g + blockRow0 * STATE);
        float4* __restrict__ dst = reinterpret_cast<float4*>(s_nsc);
        #pragma unroll 4
        for (int i = threadIdx.x; i < K2_ROWS * STATE / 4; i += K2_THREADS)
            dst[i] = __ldg(&src[i]);
    } else {
        for (int i = threadIdx.x; i < K2_ROWS * STATE; i += K2_THREADS) {
            const long long g = blockRow0 * STATE + i;
            if (g < (long long)B * STATE) s_nsc[i] = nsc_g[g];
        }
    }
    __syncthreads();

    const long long b0 = blockRow0 + threadIdx.x;
    const long long b1 = b0 + K2_THREADS;
    const bool ok0 = (b0 < B);
    const bool ok1 = (b1 < B);
    if (!ok0) return;

    const float* __restrict__ myn0 = s_nsc + threadIdx.x * STATE;
    const float* __restrict__ myn1 = myn0 + K2_THREADS * STATE;

    unsigned long long h1a[H / 2], h1b[H / 2];
    #pragma unroll
    for (int j = 0; j < H / 2; j++) { h1a[j] = 0ULL; h1b[j] = 0ULL; }

    #pragma unroll 3
    for (int d = 0; d < STATE; d++) {
        const unsigned long long v0 = pack2(myn0[d]);
        const unsigned long long v1 = pack2(myn1[d]);
        const ulonglong2* __restrict__ w1p =
            reinterpret_cast<const ulonglong2*>(&sW1[d * H]);
        #pragma unroll
        for (int q = 0; q < H / 4; q++) {
            ulonglong2 w = w1p[q];
            ffma2(h1a[q * 2 + 0], v0, w.x);
            ffma2(h1b[q * 2 + 0], v1, w.x);
            ffma2(h1a[q * 2 + 1], v0, w.y);
            ffma2(h1b[q * 2 + 1], v1, w.y);
        }
    }

    float h1x[H], h1y[H];
    #pragma unroll
    for (int j = 0; j < H / 2; j++) {
        float lo, hi;
        unpack2(h1a[j], lo, hi);
        h1x[2 * j] = fmaxf(lo, 0.0f); h1x[2 * j + 1] = fmaxf(hi, 0.0f);
        unpack2(h1b[j], lo, hi);
        h1y[2 * j] = fmaxf(lo, 0.0f); h1y[2 * j + 1] = fmaxf(hi, 0.0f);
    }

    unsigned long long h2a[H / 2], h2b[H / 2];
    #pragma unroll
    for (int j = 0; j < H / 2; j++) { h2a[j] = 0ULL; h2b[j] = 0ULL; }
    #pragma unroll
    for (int i = 0; i < H; i++) {
        const unsigned long long v0 = pack2(h1x[i]);
        const unsigned long long v1 = pack2(h1y[i]);
        const ulonglong2* __restrict__ w2p =
            reinterpret_cast<const ulonglong2*>(&sW2[i * H]);
        #pragma unroll
        for (int q = 0; q < H / 4; q++) {
            ulonglong2 w = w2p[q];
            ffma2(h2a[q * 2 + 0], v0, w.x);
            ffma2(h2b[q * 2 + 0], v1, w.x);
            ffma2(h2a[q * 2 + 1], v0, w.y);
            ffma2(h2b[q * 2 + 1], v1, w.y);
        }
    }

    float ret0 = sb3[0], ret1 = sb3[0];
    #pragma unroll
    for (int j = 0; j < H / 2; j++) {
        float lo, hi;
        unpack2(h2a[j], lo, hi);
        ret0 = fmaf(fmaxf(lo, 0.0f), sW3[2 * j + 0], ret0);
        ret0 = fmaf(fmaxf(hi, 0.0f), sW3[2 * j + 1], ret0);
        unpack2(h2b[j], lo, hi);
        ret1 = fmaf(fmaxf(lo, 0.0f), sW3[2 * j + 0], ret1);
        ret1 = fmaf(fmaxf(hi, 0.0f), sW3[2 * j + 1], ret1);
    }

    const float imm0 = out[(long long)B + b0];
    out[b0]                      = imm0 + ret0;
    out[2LL * (long long)B + b0] = ret0;
    if (ok1) {
        const float imm1 = out[(long long)B + b1];
        out[b1]                      = imm1 + ret1;
        out[2LL * (long long)B + b1] = ret1;
    }
}

static const int K2_SMEM_BYTES =
    (K2_ROWS * STATE + STATE * H + H * H + H + 1) * (int)sizeof(float);

extern "C" void kernel_launch(void* const* d_in, const int* in_sizes, int n_in,
                              void* d_out, int out_size) {
    const float* obs = (const float*)d_in[0];
    const float* action_count = (const float*)d_in[1];
    const float* W1 = (const float*)d_in[2];
    const float* W2 = (const float*)d_in[3];
    const float* W3 = (const float*)d_in[4];
    const float* b3 = (const float*)d_in[5];
    float* out = (float*)d_out;

    const int B = in_sizes[0] / (3 * STATE);

    cudaFuncSetAttribute(k2_mlp, cudaFuncAttributeMaxDynamicSharedMemorySize,
                         K2_SMEM_BYTES);

    const int blocks1 = (B + WARPS_K1 - 1) / WARPS_K1;
    k1_nsc_reward<<<blocks1, 32 * WARPS_K1>>>(obs, action_count, out, B);

    const int blocks2 = (B + K2_ROWS - 1) / K2_ROWS;
    k2_mlp<<<blocks2, K2_THREADS, K2_SMEM_BYTES>>>(W1, W2, W3, b3, out, B);
}